// round 1
// baseline (speedup 1.0000x reference)
#include <cuda_runtime.h>
#include <math.h>
#include <stdint.h>

// ---------------- problem constants ----------------
#define D128 128
#define BGR 64
#define NPG0 1024
#define NMAX (BGR * NPG0)        // 65536
#define EMAX 1048576
#define K1 820                   // ceil(0.8*1024)
#define K2 656                   // ceil(0.8*820)
#define K3 525                   // ceil(0.8*656)

// ---------------- scratch (device globals; no allocations allowed) ----------------
__device__ float g_mean[NMAX * D128];
__device__ float g_h[NMAX * D128];
__device__ float g_poolA[BGR * K1 * D128];   // also reused for layer-3 pool output
__device__ float g_poolB[BGR * K2 * D128];
__device__ float g_score[NMAX];
__device__ int   g_newid[NMAX];
__device__ int   g_src[EMAX];
__device__ int   g_dst[EMAX];
__device__ int   g_deg[NMAX];
__device__ int   g_cursor[NMAX];
__device__ int   g_rowptr[NMAX + 1];
__device__ int   g_nbr[EMAX];
__device__ float g_s[BGR * 256];

// ---------------- utility kernels ----------------
__global__ void k_zero_int(int* p, int n) {
    int i = blockIdx.x * blockDim.x + threadIdx.x;
    if (i < n) p[i] = 0;
}

__global__ void k_count(const int* __restrict__ dst, int E, int* __restrict__ deg) {
    int e = blockIdx.x * blockDim.x + threadIdx.x;
    if (e < E) {
        int d = dst[e];
        if (d >= 0) atomicAdd(&deg[d], 1);
    }
}

// single-block exclusive scan over up to 65536 ints
__global__ void k_scan(const int* __restrict__ deg, int* __restrict__ rowptr,
                       int* __restrict__ cursor, int n) {
    __shared__ int s[1024];
    int t = threadIdx.x;
    int chunk = (n + 1023) >> 10;
    int start = t * chunk;
    int end = start + chunk; if (end > n) end = n; if (start > n) start = n;
    int sum = 0;
    for (int i = start; i < end; i++) sum += deg[i];
    s[t] = sum;
    __syncthreads();
    for (int off = 1; off < 1024; off <<= 1) {
        int v = s[t];
        if (t >= off) v += s[t - off];
        __syncthreads();
        s[t] = v;
        __syncthreads();
    }
    int pre = s[t] - sum;  // exclusive prefix
    for (int i = start; i < end; i++) {
        rowptr[i] = pre;
        cursor[i] = pre;
        pre += deg[i];
    }
    if (t == 1023) rowptr[n] = s[1023];
}

__global__ void k_scatter(const int* __restrict__ src, const int* __restrict__ dst, int E,
                          int* __restrict__ cursor, int* __restrict__ nbr) {
    int e = blockIdx.x * blockDim.x + threadIdx.x;
    if (e < E) {
        int d = dst[e];
        if (d >= 0) {
            int p = atomicAdd(&cursor[d], 1);
            nbr[p] = src[e];
        }
    }
}

// one warp per dst node; mean of neighbor rows (128 features, float4 per lane)
__global__ void k_aggregate(const float* __restrict__ x, const int* __restrict__ rowptr,
                            const int* __restrict__ nbr, float* __restrict__ mean, int n) {
    int w = (blockIdx.x * blockDim.x + threadIdx.x) >> 5;
    int lane = threadIdx.x & 31;
    if (w >= n) return;
    int b = rowptr[w], e = rowptr[w + 1];
    float4 acc = make_float4(0.f, 0.f, 0.f, 0.f);
    for (int j = b; j < e; j++) {
        const float4* row = (const float4*)(x + (size_t)nbr[j] * D128);
        float4 v = row[lane];
        acc.x += v.x; acc.y += v.y; acc.z += v.z; acc.w += v.w;
    }
    int d = e - b;
    float inv = 1.0f / (float)(d > 0 ? d : 1);
    acc.x *= inv; acc.y *= inv; acc.z *= inv; acc.w *= inv;
    ((float4*)(mean + (size_t)w * D128))[lane] = acc;
}

// H = relu([mean|x] @ [Wl;Wr] + bl), classic 128x128 tile, BK=8, thread 8x8
__global__ void __launch_bounds__(256, 2)
k_gemm(const float* __restrict__ Am, const float* __restrict__ Ax,
       const float* __restrict__ Wl, const float* __restrict__ bl,
       const float* __restrict__ Wr, float* __restrict__ H, int n) {
    __shared__ float As[8][132];
    __shared__ float Bs[8][132];
    int t = threadIdx.x;
    int tx = t & 15, ty = t >> 4;
    int m0 = blockIdx.x * 128;

    float acc[8][8];
#pragma unroll
    for (int i = 0; i < 8; i++)
#pragma unroll
        for (int j = 0; j < 8; j++) acc[i][j] = 0.f;

    int mA = t >> 1;
    int kkA = (t & 1) * 4;
    int kB = t >> 5;
    int fB = (t & 31) * 4;

    for (int k0 = 0; k0 < 256; k0 += 8) {
        const float* Abase = (k0 < 128)
            ? Am + (size_t)(m0 + mA) * D128 + (k0 + kkA)
            : Ax + (size_t)(m0 + mA) * D128 + (k0 - 128 + kkA);
        float4 av = *(const float4*)Abase;
        As[kkA + 0][mA] = av.x; As[kkA + 1][mA] = av.y;
        As[kkA + 2][mA] = av.z; As[kkA + 3][mA] = av.w;

        const float* Bbase = (k0 < 128)
            ? Wl + (size_t)(k0 + kB) * D128 + fB
            : Wr + (size_t)(k0 - 128 + kB) * D128 + fB;
        *(float4*)&Bs[kB][fB] = *(const float4*)Bbase;
        __syncthreads();

#pragma unroll
        for (int kk = 0; kk < 8; kk++) {
            float4 a0 = *(float4*)&As[kk][ty * 8];
            float4 a1 = *(float4*)&As[kk][ty * 8 + 4];
            float4 b0 = *(float4*)&Bs[kk][tx * 8];
            float4 b1 = *(float4*)&Bs[kk][tx * 8 + 4];
            float a[8] = {a0.x, a0.y, a0.z, a0.w, a1.x, a1.y, a1.z, a1.w};
            float b[8] = {b0.x, b0.y, b0.z, b0.w, b1.x, b1.y, b1.z, b1.w};
#pragma unroll
            for (int i = 0; i < 8; i++)
#pragma unroll
                for (int j = 0; j < 8; j++) acc[i][j] += a[i] * b[j];
        }
        __syncthreads();
    }

    float bb[8];
#pragma unroll
    for (int j = 0; j < 8; j++) bb[j] = bl[tx * 8 + j];
#pragma unroll
    for (int i = 0; i < 8; i++) {
        int row = m0 + ty * 8 + i;
        if (row < n) {
            float4 o0, o1;
            o0.x = fmaxf(acc[i][0] + bb[0], 0.f);
            o0.y = fmaxf(acc[i][1] + bb[1], 0.f);
            o0.z = fmaxf(acc[i][2] + bb[2], 0.f);
            o0.w = fmaxf(acc[i][3] + bb[3], 0.f);
            o1.x = fmaxf(acc[i][4] + bb[4], 0.f);
            o1.y = fmaxf(acc[i][5] + bb[5], 0.f);
            o1.z = fmaxf(acc[i][6] + bb[6], 0.f);
            o1.w = fmaxf(acc[i][7] + bb[7], 0.f);
            float* hp = H + (size_t)row * D128 + tx * 8;
            *(float4*)hp = o0;
            *(float4*)(hp + 4) = o1;
        }
    }
}

// score[i] = tanh(h_i . pw / ||pw||), one warp per row
__global__ void k_score(const float* __restrict__ H, const float* __restrict__ pw,
                        float* __restrict__ score, int n) {
    int w = (blockIdx.x * blockDim.x + threadIdx.x) >> 5;
    int lane = threadIdx.x & 31;
    if (w >= n) return;
    float4 h4 = ((const float4*)(H + (size_t)w * D128))[lane];
    float4 w4 = ((const float4*)pw)[lane];
    float dot = h4.x * w4.x + h4.y * w4.y + h4.z * w4.z + h4.w * w4.w;
    float nn = w4.x * w4.x + w4.y * w4.y + w4.z * w4.z + w4.w * w4.w;
#pragma unroll
    for (int off = 16; off > 0; off >>= 1) {
        dot += __shfl_xor_sync(0xFFFFFFFF, dot, off);
        nn  += __shfl_xor_sync(0xFFFFFFFF, nn, off);
    }
    if (lane == 0) score[w] = tanhf(dot / sqrtf(nn));
}

// per-graph bitonic top-K; writes newid + pooled features (x_new = h[sel]*score)
__global__ void k_topk(const float* __restrict__ score, const float* __restrict__ H,
                       float* __restrict__ pool, int* __restrict__ newid, int Npg, int K) {
    __shared__ float skey[1024];
    __shared__ int   sidx[1024];
    int g = blockIdx.x;
    int t = threadIdx.x;   // 512 threads
    for (int i = t; i < 1024; i += 512) {
        if (i < Npg) { skey[i] = score[g * Npg + i]; }
        else         { skey[i] = -INFINITY; }
        sidx[i] = i;
    }
    __syncthreads();
    for (int k = 2; k <= 1024; k <<= 1) {
        for (int j = k >> 1; j > 0; j >>= 1) {
            for (int i = t; i < 1024; i += 512) {
                int ixj = i ^ j;
                if (ixj > i) {
                    bool desc = ((i & k) == 0);
                    float a = skey[i], b = skey[ixj];
                    bool sw = desc ? (a < b) : (a > b);
                    if (sw) {
                        skey[i] = b; skey[ixj] = a;
                        int tmp = sidx[i]; sidx[i] = sidx[ixj]; sidx[ixj] = tmp;
                    }
                }
            }
            __syncthreads();
        }
    }
    for (int i = t; i < Npg; i += 512) {
        int node = sidx[i];
        newid[g * Npg + node] = (i < K) ? (g * K + i) : -1;
    }
    __syncthreads();
    int total = K * D128;
    for (int l = t; l < total; l += 512) {
        int r = l >> 7, f = l & 127;
        int node = sidx[r];
        pool[(size_t)(g * K + r) * D128 + f] =
            H[(size_t)(g * Npg + node) * D128 + f] * skey[r];
    }
}

// readout: s[g] (+)= [max || mean] over K pooled rows
__global__ void k_readout(const float* __restrict__ pool, int K, float* __restrict__ s_out,
                          int round) {
    int g = blockIdx.x, f = threadIdx.x;  // 128 threads
    float mx = -INFINITY, sm = 0.f;
    for (int r = 0; r < K; r++) {
        float v = pool[(size_t)(g * K + r) * D128 + f];
        mx = fmaxf(mx, v);
        sm += v;
    }
    float mean = sm / (float)K;
    if (round == 0) {
        s_out[g * 256 + f] = mx;
        s_out[g * 256 + 128 + f] = mean;
    } else {
        s_out[g * 256 + f] += mx;
        s_out[g * 256 + 128 + f] += mean;
    }
}

__global__ void k_remap(const int* __restrict__ src_in, const int* __restrict__ dst_in,
                        int* __restrict__ src_out, int* __restrict__ dst_out,
                        const int* __restrict__ newid, int E) {
    int e = blockIdx.x * blockDim.x + threadIdx.x;
    if (e >= E) return;
    int s = src_in[e], d = dst_in[e];
    int ns = -1, nd = -1;
    if (s >= 0 && d >= 0) { ns = newid[s]; nd = newid[d]; }
    if (ns < 0 || nd < 0) { src_out[e] = -1; dst_out[e] = -1; }
    else                  { src_out[e] = ns; dst_out[e] = nd; }
}

// final MLP: 256->128->64->1 + sigmoid, one block (128 threads) per graph
__global__ void k_mlp(const float* __restrict__ s,
                      const float* __restrict__ W1, const float* __restrict__ b1,
                      const float* __restrict__ W2, const float* __restrict__ b2,
                      const float* __restrict__ W3, const float* __restrict__ b3,
                      float* __restrict__ out) {
    __shared__ float sh[256];
    __shared__ float h1[128];
    __shared__ float h2[64];
    __shared__ float red[128];
    int g = blockIdx.x, t = threadIdx.x;  // 128 threads
    sh[t] = s[g * 256 + t];
    sh[t + 128] = s[g * 256 + 128 + t];
    __syncthreads();
    float acc = b1[t];
    for (int k = 0; k < 256; k++) acc += sh[k] * W1[k * 128 + t];
    h1[t] = fmaxf(acc, 0.f);
    __syncthreads();
    if (t < 64) {
        float a = b2[t];
        for (int k = 0; k < 128; k++) a += h1[k] * W2[k * 64 + t];
        h2[t] = fmaxf(a, 0.f);
    }
    __syncthreads();
    red[t] = (t < 64) ? h2[t] * W3[t] : 0.f;
    __syncthreads();
    for (int off = 64; off > 0; off >>= 1) {
        if (t < off) red[t] += red[t + off];
        __syncthreads();
    }
    if (t == 0) out[g] = 1.f / (1.f + expf(-(red[0] + b3[0])));
}

// ---------------- host orchestration ----------------
extern "C" void kernel_launch(void* const* d_in, const int* in_sizes, int n_in,
                              void* d_out, int out_size) {
    const float* x   = (const float*)d_in[0];
    const int*   ei  = (const int*)d_in[1];
    const int E = in_sizes[1] / 2;

    const float* Wl1 = (const float*)d_in[2];
    const float* bl1 = (const float*)d_in[3];
    const float* Wr1 = (const float*)d_in[4];
    const float* pw1 = (const float*)d_in[5];
    const float* Wl2 = (const float*)d_in[6];
    const float* bl2 = (const float*)d_in[7];
    const float* Wr2 = (const float*)d_in[8];
    const float* pw2 = (const float*)d_in[9];
    const float* Wl3 = (const float*)d_in[10];
    const float* bl3 = (const float*)d_in[11];
    const float* Wr3 = (const float*)d_in[12];
    const float* pw3 = (const float*)d_in[13];
    const float* W1  = (const float*)d_in[14];
    const float* b1  = (const float*)d_in[15];
    const float* W2  = (const float*)d_in[16];
    const float* b2  = (const float*)d_in[17];
    const float* W3  = (const float*)d_in[18];
    const float* b3  = (const float*)d_in[19];

    float *meanP, *hP, *poolA, *poolB, *scoreP, *sP;
    int *newidP, *srcP, *dstP, *degP, *curP, *rpP, *nbrP;
    cudaGetSymbolAddress((void**)&meanP, g_mean);
    cudaGetSymbolAddress((void**)&hP, g_h);
    cudaGetSymbolAddress((void**)&poolA, g_poolA);
    cudaGetSymbolAddress((void**)&poolB, g_poolB);
    cudaGetSymbolAddress((void**)&scoreP, g_score);
    cudaGetSymbolAddress((void**)&sP, g_s);
    cudaGetSymbolAddress((void**)&newidP, g_newid);
    cudaGetSymbolAddress((void**)&srcP, g_src);
    cudaGetSymbolAddress((void**)&dstP, g_dst);
    cudaGetSymbolAddress((void**)&degP, g_deg);
    cudaGetSymbolAddress((void**)&curP, g_cursor);
    cudaGetSymbolAddress((void**)&rpP, g_rowptr);
    cudaGetSymbolAddress((void**)&nbrP, g_nbr);

    const int TB = 256;
    const int EB = (E + TB - 1) / TB;

    struct LayerCfg {
        const float *xin, *Wl, *bl, *Wr, *pw;
        float* pool;
        int n, Npg, K, round;
        const int *esrc, *edst;
    };
    LayerCfg layers[3] = {
        { x,     Wl1, bl1, Wr1, pw1, poolA, BGR * NPG0, NPG0, K1, 0, ei,   ei + E },
        { poolA, Wl2, bl2, Wr2, pw2, poolB, BGR * K1,   K1,   K2, 1, srcP, dstP   },
        { poolB, Wl3, bl3, Wr3, pw3, poolA, BGR * K2,   K2,   K3, 2, srcP, dstP   },
    };

    for (int L = 0; L < 3; L++) {
        LayerCfg& c = layers[L];
        int n = c.n;
        // CSR build
        k_zero_int<<<(n + TB - 1) / TB, TB>>>(degP, n);
        k_count<<<EB, TB>>>(c.edst, E, degP);
        k_scan<<<1, 1024>>>(degP, rpP, curP, n);
        k_scatter<<<EB, TB>>>(c.esrc, c.edst, E, curP, nbrP);
        // mean aggregation
        k_aggregate<<<(n * 32 + TB - 1) / TB, TB>>>(c.xin, rpP, nbrP, meanP, n);
        // SAGE linear + relu
        k_gemm<<<(n + 127) / 128, 256>>>(meanP, c.xin, c.Wl, c.bl, c.Wr, hP, n);
        // topk score
        k_score<<<(n * 32 + TB - 1) / TB, TB>>>(hP, c.pw, scoreP, n);
        // pooling
        k_topk<<<BGR, 512>>>(scoreP, hP, c.pool, newidP, c.Npg, c.K);
        // readout accumulate
        k_readout<<<BGR, 128>>>(c.pool, c.K, sP, c.round);
        // edge remap for next layer (harmless extra on last layer)
        if (L < 2) k_remap<<<EB, TB>>>(c.esrc, c.edst, srcP, dstP, newidP, E);
    }

    k_mlp<<<BGR, 128>>>(sP, W1, b1, W2, b2, W3, b3, (float*)d_out);
}

// round 3
// speedup vs baseline: 1.1737x; 1.1737x over previous
#include <cuda_runtime.h>
#include <math.h>
#include <stdint.h>

// ---------------- problem constants ----------------
#define D128 128
#define BGR 64
#define NPG0 1024
#define NMAX (BGR * NPG0)        // 65536
#define EMAX 1048576
#define K1 820                   // ceil(0.8*1024)
#define K2 656                   // ceil(0.8*820)
#define K3 525                   // ceil(0.8*656)

// ---------------- scratch (device globals; no allocations allowed) ----------------
__device__ float g_mean[NMAX * D128];
__device__ float g_h[NMAX * D128];
__device__ float g_poolA[BGR * K1 * D128];
__device__ float g_poolB[BGR * K2 * D128];
__device__ float g_score[NMAX];
__device__ int   g_newid[NMAX];
__device__ int   g_src[EMAX];
__device__ int   g_dst[EMAX];
__device__ int   g_deg[NMAX];
__device__ int   g_cursor[NMAX];
__device__ int   g_rowptr[NMAX + 1];
__device__ int   g_nbr[EMAX];
__device__ float g_s[BGR * 256];

// ---------------- utility kernels ----------------
__global__ void k_zero_int(int* p, int n) {
    int i = blockIdx.x * blockDim.x + threadIdx.x;
    if (i < n) p[i] = 0;
}

__global__ void k_count(const int* __restrict__ dst, int E, int* __restrict__ deg) {
    int e = blockIdx.x * blockDim.x + threadIdx.x;
    if (e < E) {
        int d = dst[e];
        if (d >= 0) atomicAdd(&deg[d], 1);
    }
}

__global__ void k_scan(const int* __restrict__ deg, int* __restrict__ rowptr,
                       int* __restrict__ cursor, int n) {
    __shared__ int s[1024];
    int t = threadIdx.x;
    int chunk = (n + 1023) >> 10;
    int start = t * chunk;
    int end = start + chunk; if (end > n) end = n; if (start > n) start = n;
    int sum = 0;
    for (int i = start; i < end; i++) sum += deg[i];
    s[t] = sum;
    __syncthreads();
    for (int off = 1; off < 1024; off <<= 1) {
        int v = s[t];
        if (t >= off) v += s[t - off];
        __syncthreads();
        s[t] = v;
        __syncthreads();
    }
    int pre = s[t] - sum;
    for (int i = start; i < end; i++) {
        rowptr[i] = pre;
        cursor[i] = pre;
        pre += deg[i];
    }
    if (t == 1023) rowptr[n] = s[1023];
}

__global__ void k_scatter(const int* __restrict__ src, const int* __restrict__ dst, int E,
                          int* __restrict__ cursor, int* __restrict__ nbr) {
    int e = blockIdx.x * blockDim.x + threadIdx.x;
    if (e < E) {
        int d = dst[e];
        if (d >= 0) {
            int p = atomicAdd(&cursor[d], 1);
            nbr[p] = src[e];
        }
    }
}

__global__ void k_aggregate(const float* __restrict__ x, const int* __restrict__ rowptr,
                            const int* __restrict__ nbr, float* __restrict__ mean, int n) {
    int w = (blockIdx.x * blockDim.x + threadIdx.x) >> 5;
    int lane = threadIdx.x & 31;
    if (w >= n) return;
    int b = rowptr[w], e = rowptr[w + 1];
    float4 acc = make_float4(0.f, 0.f, 0.f, 0.f);
    for (int j = b; j < e; j++) {
        const float4* row = (const float4*)(x + (size_t)nbr[j] * D128);
        float4 v = row[lane];
        acc.x += v.x; acc.y += v.y; acc.z += v.z; acc.w += v.w;
    }
    int d = e - b;
    float inv = 1.0f / (float)(d > 0 ? d : 1);
    acc.x *= inv; acc.y *= inv; acc.z *= inv; acc.w *= inv;
    ((float4*)(mean + (size_t)w * D128))[lane] = acc;
}

// ---------------- tf32 mma.sync GEMM: H = relu([mean|x] @ [Wl;Wr] + bl) ----------------
// CTA tile 128x128, K=256 in 8 chunks of 32. 8 warps, warp tile 64x32 (4x4 m16n8k8 frags).
// fp32 staged in SMEM; 3xTF32 split done in registers (hi*hi + hi*lo + lo*hi).
#define ASTRIDE 36    // 128x32 A tile, padded row stride (floats)
#define BSTRIDE 136   // 32x128 B tile, padded row stride (floats)

__device__ __forceinline__ void mma_m16n8k8(float* c, const uint32_t* a, const uint32_t* b) {
    asm volatile(
        "mma.sync.aligned.m16n8k8.row.col.f32.tf32.tf32.f32 "
        "{%0,%1,%2,%3}, {%4,%5,%6,%7}, {%8,%9}, {%0,%1,%2,%3};"
        : "+f"(c[0]), "+f"(c[1]), "+f"(c[2]), "+f"(c[3])
        : "r"(a[0]), "r"(a[1]), "r"(a[2]), "r"(a[3]), "r"(b[0]), "r"(b[1]));
}

__device__ __forceinline__ void tf32_split(float v, uint32_t& hi, uint32_t& lo) {
    asm("cvt.rna.tf32.f32 %0, %1;" : "=r"(hi) : "f"(v));
    float r = v - __uint_as_float(hi);
    asm("cvt.rna.tf32.f32 %0, %1;" : "=r"(lo) : "f"(r));
}

__global__ void __launch_bounds__(256, 2)
k_gemm_mma(const float* __restrict__ Am, const float* __restrict__ Ax,
           const float* __restrict__ Wl, const float* __restrict__ bl,
           const float* __restrict__ Wr, float* __restrict__ H, int n) {
    __shared__ float As[128 * ASTRIDE];
    __shared__ float Bs[32 * BSTRIDE];
    int t = threadIdx.x, lane = t & 31, wid = t >> 5;
    int wm = (wid >> 2) * 64;     // warp m offset (0 or 64)
    int wn = (wid & 3) * 32;      // warp n offset
    int m0 = blockIdx.x * 128;

    float c[4][4][4];
#pragma unroll
    for (int i = 0; i < 4; i++)
#pragma unroll
        for (int j = 0; j < 4; j++)
#pragma unroll
            for (int r = 0; r < 4; r++) c[i][j][r] = 0.f;

    int arow = t >> 1, acol0 = (t & 1) * 16;
    int brow = t >> 3, bq0 = t & 7;

    for (int ch = 0; ch < 8; ch++) {
        // load A chunk [128 x 32]
        const float* A = (ch < 4) ? Am + (size_t)m0 * D128 + ch * 32
                                  : Ax + (size_t)m0 * D128 + (ch - 4) * 32;
        {
            const float4* s = (const float4*)(A + (size_t)arow * D128 + acol0);
            float* d = As + arow * ASTRIDE + acol0;
#pragma unroll
            for (int q = 0; q < 4; q++) *(float4*)(d + q * 4) = s[q];
        }
        // load B chunk [32 x 128]
        const float* W = (ch < 4) ? Wl + (size_t)(ch * 32) * D128
                                  : Wr + (size_t)((ch - 4) * 32) * D128;
        {
#pragma unroll
            for (int q = 0; q < 4; q++) {
                int col = (bq0 + q * 8) * 4;
                *(float4*)(Bs + brow * BSTRIDE + col) =
                    *(const float4*)(W + (size_t)brow * D128 + col);
            }
        }
        __syncthreads();

#pragma unroll
        for (int ks = 0; ks < 4; ks++) {
            uint32_t ah[4][4], al[4][4], bh[4][2], blo[4][2];
#pragma unroll
            for (int mf = 0; mf < 4; mf++)
#pragma unroll
                for (int r = 0; r < 4; r++) {
                    float v = As[(wm + mf * 16 + (lane >> 2) + 8 * (r & 1)) * ASTRIDE
                                 + ks * 8 + (lane & 3) + 4 * (r >> 1)];
                    tf32_split(v, ah[mf][r], al[mf][r]);
                }
#pragma unroll
            for (int nf = 0; nf < 4; nf++)
#pragma unroll
                for (int r = 0; r < 2; r++) {
                    float v = Bs[(ks * 8 + (lane & 3) + 4 * r) * BSTRIDE
                                 + wn + nf * 8 + (lane >> 2)];
                    tf32_split(v, bh[nf][r], blo[nf][r]);
                }
#pragma unroll
            for (int mf = 0; mf < 4; mf++)
#pragma unroll
                for (int nf = 0; nf < 4; nf++) {
                    mma_m16n8k8(c[mf][nf], ah[mf], bh[nf]);
                    mma_m16n8k8(c[mf][nf], ah[mf], blo[nf]);
                    mma_m16n8k8(c[mf][nf], al[mf], bh[nf]);
                }
        }
        __syncthreads();
    }

    // epilogue: bias + relu; C frag: rows lane/4 (+8), cols 2*(lane%4) (+1)
    int r0 = lane >> 2, cq = (lane & 3) * 2;
#pragma unroll
    for (int mf = 0; mf < 4; mf++) {
        int row = m0 + wm + mf * 16 + r0;
#pragma unroll
        for (int nf = 0; nf < 4; nf++) {
            int col = wn + nf * 8 + cq;
            float b0 = bl[col], b1 = bl[col + 1];
            float2 o0, o1;
            o0.x = fmaxf(c[mf][nf][0] + b0, 0.f);
            o0.y = fmaxf(c[mf][nf][1] + b1, 0.f);
            o1.x = fmaxf(c[mf][nf][2] + b0, 0.f);
            o1.y = fmaxf(c[mf][nf][3] + b1, 0.f);
            *(float2*)(H + (size_t)row * D128 + col) = o0;
            *(float2*)(H + (size_t)(row + 8) * D128 + col) = o1;
        }
    }
}

// score[i] = tanh(h_i . pw / ||pw||), one warp per row
__global__ void k_score(const float* __restrict__ H, const float* __restrict__ pw,
                        float* __restrict__ score, int n) {
    int w = (blockIdx.x * blockDim.x + threadIdx.x) >> 5;
    int lane = threadIdx.x & 31;
    if (w >= n) return;
    float4 h4 = ((const float4*)(H + (size_t)w * D128))[lane];
    float4 w4 = ((const float4*)pw)[lane];
    float dot = h4.x * w4.x + h4.y * w4.y + h4.z * w4.z + h4.w * w4.w;
    float nn = w4.x * w4.x + w4.y * w4.y + w4.z * w4.z + w4.w * w4.w;
#pragma unroll
    for (int off = 16; off > 0; off >>= 1) {
        dot += __shfl_xor_sync(0xFFFFFFFF, dot, off);
        nn  += __shfl_xor_sync(0xFFFFFFFF, nn, off);
    }
    if (lane == 0) score[w] = tanhf(dot / sqrtf(nn));
}

// per-graph bitonic top-K
__global__ void k_topk(const float* __restrict__ score, const float* __restrict__ H,
                       float* __restrict__ pool, int* __restrict__ newid, int Npg, int K) {
    __shared__ float skey[1024];
    __shared__ int   sidx[1024];
    int g = blockIdx.x;
    int t = threadIdx.x;   // 512 threads
    for (int i = t; i < 1024; i += 512) {
        if (i < Npg) { skey[i] = score[g * Npg + i]; }
        else         { skey[i] = -INFINITY; }
        sidx[i] = i;
    }
    __syncthreads();
    for (int k = 2; k <= 1024; k <<= 1) {
        for (int j = k >> 1; j > 0; j >>= 1) {
            for (int i = t; i < 1024; i += 512) {
                int ixj = i ^ j;
                if (ixj > i) {
                    bool desc = ((i & k) == 0);
                    float a = skey[i], b = skey[ixj];
                    bool sw = desc ? (a < b) : (a > b);
                    if (sw) {
                        skey[i] = b; skey[ixj] = a;
                        int tmp = sidx[i]; sidx[i] = sidx[ixj]; sidx[ixj] = tmp;
                    }
                }
            }
            __syncthreads();
        }
    }
    for (int i = t; i < Npg; i += 512) {
        int node = sidx[i];
        newid[g * Npg + node] = (i < K) ? (g * K + i) : -1;
    }
    __syncthreads();
    int total = K * D128;
    for (int l = t; l < total; l += 512) {
        int r = l >> 7, f = l & 127;
        int node = sidx[r];
        pool[(size_t)(g * K + r) * D128 + f] =
            H[(size_t)(g * Npg + node) * D128 + f] * skey[r];
    }
}

// readout: s[g] (+)= [max || mean] over K pooled rows; 512 threads, 4-way row split
__global__ void k_readout(const float* __restrict__ pool, int K, float* __restrict__ s_out,
                          int round) {
    __shared__ float smx[4][128];
    __shared__ float ssm[4][128];
    int g = blockIdx.x, t = threadIdx.x;
    int f = t & 127, part = t >> 7;
    float mx = -INFINITY, sm = 0.f;
    for (int r = part; r < K; r += 4) {
        float v = pool[(size_t)(g * K + r) * D128 + f];
        mx = fmaxf(mx, v);
        sm += v;
    }
    smx[part][f] = mx; ssm[part][f] = sm;
    __syncthreads();
    if (part == 0) {
        float m2 = fmaxf(fmaxf(smx[0][f], smx[1][f]), fmaxf(smx[2][f], smx[3][f]));
        float s2 = ssm[0][f] + ssm[1][f] + ssm[2][f] + ssm[3][f];
        float mean = s2 / (float)K;
        if (round == 0) {
            s_out[g * 256 + f] = m2;
            s_out[g * 256 + 128 + f] = mean;
        } else {
            s_out[g * 256 + f] += m2;
            s_out[g * 256 + 128 + f] += mean;
        }
    }
}

__global__ void k_remap(const int* __restrict__ src_in, const int* __restrict__ dst_in,
                        int* __restrict__ src_out, int* __restrict__ dst_out,
                        const int* __restrict__ newid, int E) {
    int e = blockIdx.x * blockDim.x + threadIdx.x;
    if (e >= E) return;
    int s = src_in[e], d = dst_in[e];
    int ns = -1, nd = -1;
    if (s >= 0 && d >= 0) { ns = newid[s]; nd = newid[d]; }
    if (ns < 0 || nd < 0) { src_out[e] = -1; dst_out[e] = -1; }
    else                  { src_out[e] = ns; dst_out[e] = nd; }
}

// final MLP: 256->128->64->1 + sigmoid
__global__ void k_mlp(const float* __restrict__ s,
                      const float* __restrict__ W1, const float* __restrict__ b1,
                      const float* __restrict__ W2, const float* __restrict__ b2,
                      const float* __restrict__ W3, const float* __restrict__ b3,
                      float* __restrict__ out) {
    __shared__ float sh[256];
    __shared__ float h1[128];
    __shared__ float h2[64];
    __shared__ float red[128];
    int g = blockIdx.x, t = threadIdx.x;
    sh[t] = s[g * 256 + t];
    sh[t + 128] = s[g * 256 + 128 + t];
    __syncthreads();
    float acc = b1[t];
    for (int k = 0; k < 256; k++) acc += sh[k] * W1[k * 128 + t];
    h1[t] = fmaxf(acc, 0.f);
    __syncthreads();
    if (t < 64) {
        float a = b2[t];
        for (int k = 0; k < 128; k++) a += h1[k] * W2[k * 64 + t];
        h2[t] = fmaxf(a, 0.f);
    }
    __syncthreads();
    red[t] = (t < 64) ? h2[t] * W3[t] : 0.f;
    __syncthreads();
    for (int off = 64; off > 0; off >>= 1) {
        if (t < off) red[t] += red[t + off];
        __syncthreads();
    }
    if (t == 0) out[g] = 1.f / (1.f + expf(-(red[0] + b3[0])));
}

// ---------------- host orchestration ----------------
extern "C" void kernel_launch(void* const* d_in, const int* in_sizes, int n_in,
                              void* d_out, int out_size) {
    const float* x   = (const float*)d_in[0];
    const int*   ei  = (const int*)d_in[1];
    const int E = in_sizes[1] / 2;

    const float* Wl1 = (const float*)d_in[2];
    const float* bl1 = (const float*)d_in[3];
    const float* Wr1 = (const float*)d_in[4];
    const float* pw1 = (const float*)d_in[5];
    const float* Wl2 = (const float*)d_in[6];
    const float* bl2 = (const float*)d_in[7];
    const float* Wr2 = (const float*)d_in[8];
    const float* pw2 = (const float*)d_in[9];
    const float* Wl3 = (const float*)d_in[10];
    const float* bl3 = (const float*)d_in[11];
    const float* Wr3 = (const float*)d_in[12];
    const float* pw3 = (const float*)d_in[13];
    const float* W1  = (const float*)d_in[14];
    const float* b1  = (const float*)d_in[15];
    const float* W2  = (const float*)d_in[16];
    const float* b2  = (const float*)d_in[17];
    const float* W3  = (const float*)d_in[18];
    const float* b3  = (const float*)d_in[19];

    float *meanP, *hP, *poolA, *poolB, *scoreP, *sP;
    int *newidP, *srcP, *dstP, *degP, *curP, *rpP, *nbrP;
    cudaGetSymbolAddress((void**)&meanP, g_mean);
    cudaGetSymbolAddress((void**)&hP, g_h);
    cudaGetSymbolAddress((void**)&poolA, g_poolA);
    cudaGetSymbolAddress((void**)&poolB, g_poolB);
    cudaGetSymbolAddress((void**)&scoreP, g_score);
    cudaGetSymbolAddress((void**)&sP, g_s);
    cudaGetSymbolAddress((void**)&newidP, g_newid);
    cudaGetSymbolAddress((void**)&srcP, g_src);
    cudaGetSymbolAddress((void**)&dstP, g_dst);
    cudaGetSymbolAddress((void**)&degP, g_deg);
    cudaGetSymbolAddress((void**)&curP, g_cursor);
    cudaGetSymbolAddress((void**)&rpP, g_rowptr);
    cudaGetSymbolAddress((void**)&nbrP, g_nbr);

    const int TB = 256;
    const int EB = (E + TB - 1) / TB;

    struct LayerCfg {
        const float *xin, *Wl, *bl, *Wr, *pw;
        float* pool;
        int n, Npg, K, round;
        const int *esrc, *edst;
    };
    LayerCfg layers[3] = {
        { x,     Wl1, bl1, Wr1, pw1, poolA, BGR * NPG0, NPG0, K1, 0, ei,   ei + E },
        { poolA, Wl2, bl2, Wr2, pw2, poolB, BGR * K1,   K1,   K2, 1, srcP, dstP   },
        { poolB, Wl3, bl3, Wr3, pw3, poolA, BGR * K2,   K2,   K3, 2, srcP, dstP   },
    };

    for (int L = 0; L < 3; L++) {
        LayerCfg& c = layers[L];
        int n = c.n;
        // CSR build
        k_zero_int<<<(n + TB - 1) / TB, TB>>>(degP, n);
        k_count<<<EB, TB>>>(c.edst, E, degP);
        k_scan<<<1, 1024>>>(degP, rpP, curP, n);
        k_scatter<<<EB, TB>>>(c.esrc, c.edst, E, curP, nbrP);
        // mean aggregation
        k_aggregate<<<(n * 32 + TB - 1) / TB, TB>>>(c.xin, rpP, nbrP, meanP, n);
        // SAGE linear + relu (tf32 mma.sync, 3x split)
        k_gemm_mma<<<n / 128, 256>>>(meanP, c.xin, c.Wl, c.bl, c.Wr, hP, n);
        // topk score
        k_score<<<(n * 32 + TB - 1) / TB, TB>>>(hP, c.pw, scoreP, n);
        // pooling
        k_topk<<<BGR, 512>>>(scoreP, hP, c.pool, newidP, c.Npg, c.K);
        // readout accumulate
        k_readout<<<BGR, 512>>>(c.pool, c.K, sP, c.round);
        // edge remap for next layer
        if (L < 2) k_remap<<<EB, TB>>>(c.esrc, c.edst, srcP, dstP, newidP, E);
    }

    k_mlp<<<BGR, 128>>>(sP, W1, b1, W2, b2, W3, b3, (float*)d_out);
}

// round 4
// speedup vs baseline: 1.8556x; 1.5810x over previous
#include <cuda_runtime.h>
#include <math.h>
#include <stdint.h>

// ---------------- problem constants ----------------
#define D128 128
#define BGR 64
#define NPG0 1024
#define NMAX (BGR * NPG0)        // 65536
#define EMAX 1048576
#define K1 820                   // ceil(0.8*1024)
#define K2 656                   // ceil(0.8*820)
#define K3 525                   // ceil(0.8*656)

// ---------------- scratch (device globals; no allocations allowed) ----------------
__device__ float g_mean[NMAX * D128];
__device__ float g_h[NMAX * D128];
__device__ float g_poolA[BGR * K1 * D128];
__device__ float g_poolB[BGR * K2 * D128];
__device__ float g_score[NMAX];
__device__ int   g_newid[NMAX];
__device__ int   g_orig2cur[NMAX];
__device__ int   g_cur2orig[NMAX];
__device__ int   g_deg[NMAX];
__device__ int   g_cursor[NMAX];
__device__ int   g_rowptr[NMAX + 1];
__device__ int   g_nbr[EMAX];
__device__ int   g_part[64];
__device__ int   g_offs[64];
__device__ float g_bhi[256 * D128];
__device__ float g_blo[256 * D128];
__device__ float g_s[BGR * 256];

__device__ __forceinline__ void tf32_split(float v, uint32_t& hi, uint32_t& lo) {
    asm("cvt.rna.tf32.f32 %0, %1;" : "=r"(hi) : "f"(v));
    float r = v - __uint_as_float(hi);
    asm("cvt.rna.tf32.f32 %0, %1;" : "=r"(lo) : "f"(r));
}

__device__ __forceinline__ void mma_m16n8k8(float* c, const uint32_t* a, const uint32_t* b) {
    asm volatile(
        "mma.sync.aligned.m16n8k8.row.col.f32.tf32.tf32.f32 "
        "{%0,%1,%2,%3}, {%4,%5,%6,%7}, {%8,%9}, {%0,%1,%2,%3};"
        : "+f"(c[0]), "+f"(c[1]), "+f"(c[2]), "+f"(c[3])
        : "r"(a[0]), "r"(a[1]), "r"(a[2]), "r"(a[3]), "r"(b[0]), "r"(b[1]));
}

// ---------------- CSR build (once, on original graph) ----------------
__global__ void k_zero_int(int* p, int n) {
    int i = blockIdx.x * blockDim.x + threadIdx.x;
    if (i < n) p[i] = 0;
}

__global__ void k_count(const int* __restrict__ dst, int E, int* __restrict__ deg) {
    int e = blockIdx.x * blockDim.x + threadIdx.x;
    if (e < E) atomicAdd(&deg[dst[e]], 1);
}

// 64 blocks x 1024: block sums
__global__ void k_scan1(const int* __restrict__ deg, int* __restrict__ part) {
    __shared__ int s[1024];
    int t = threadIdx.x;
    s[t] = deg[blockIdx.x * 1024 + t];
    __syncthreads();
    for (int off = 512; off > 0; off >>= 1) {
        if (t < off) s[t] += s[t + off];
        __syncthreads();
    }
    if (t == 0) part[blockIdx.x] = s[0];
}

// 1 block x 64: exclusive scan of partials
__global__ void k_scan2(const int* __restrict__ part, int* __restrict__ offs) {
    __shared__ int s[64];
    int t = threadIdx.x;
    int my = part[t];
    s[t] = my;
    __syncthreads();
    for (int off = 1; off < 64; off <<= 1) {
        int v = s[t];
        if (t >= off) v += s[t - off];
        __syncthreads();
        s[t] = v;
        __syncthreads();
    }
    offs[t] = s[t] - my;
}

// 64 blocks x 1024: block-local exclusive scan + offset
__global__ void k_scan3(const int* __restrict__ deg, const int* __restrict__ offs,
                        int* __restrict__ rowptr, int* __restrict__ cursor, int n) {
    __shared__ int s[1024];
    int t = threadIdx.x;
    int i = blockIdx.x * 1024 + t;
    int my = deg[i];
    s[t] = my;
    __syncthreads();
    for (int off = 1; off < 1024; off <<= 1) {
        int v = s[t];
        if (t >= off) v += s[t - off];
        __syncthreads();
        s[t] = v;
        __syncthreads();
    }
    int ex = s[t] - my + offs[blockIdx.x];
    rowptr[i] = ex;
    cursor[i] = ex;
    if (blockIdx.x == 63 && t == 1023) rowptr[n] = ex + my;
}

__global__ void k_scatter(const int* __restrict__ src, const int* __restrict__ dst, int E,
                          int* __restrict__ cursor, int* __restrict__ nbr) {
    int e = blockIdx.x * blockDim.x + threadIdx.x;
    if (e < E) {
        int p = atomicAdd(&cursor[dst[e]], 1);
        nbr[p] = src[e];
    }
}

__global__ void k_initmaps(int* __restrict__ o2c, int* __restrict__ c2o) {
    int i = blockIdx.x * blockDim.x + threadIdx.x;
    if (i < NMAX) { o2c[i] = i; c2o[i] = i; }
}

// compose pooling into maps: orig2cur <- newid o orig2cur; cur2orig = inverse
__global__ void k_compose(int* __restrict__ o2c, int* __restrict__ c2o,
                          const int* __restrict__ newid) {
    int o = blockIdx.x * blockDim.x + threadIdx.x;
    if (o >= NMAX) return;
    int c = o2c[o];
    int nc = (c >= 0) ? newid[c] : -1;
    o2c[o] = nc;
    if (nc >= 0) c2o[nc] = o;
}

// ---------------- mean aggregation over reusable original CSR ----------------
__global__ void k_aggregate(const float* __restrict__ X, const int* __restrict__ rowptr,
                            const int* __restrict__ nbr, const int* __restrict__ c2o,
                            const int* __restrict__ o2c, float* __restrict__ mean, int n) {
    int w = (blockIdx.x * blockDim.x + threadIdx.x) >> 5;
    int lane = threadIdx.x & 31;
    if (w >= n) return;
    int o = c2o[w];
    int b = rowptr[o], e = rowptr[o + 1];
    float4 acc = make_float4(0.f, 0.f, 0.f, 0.f);
    float cnt = 0.f;
#pragma unroll 4
    for (int j = b; j < e; j++) {
        int c = o2c[nbr[j]];
        float wgt = (c >= 0) ? 1.f : 0.f;
        int idx = (c >= 0) ? c : 0;
        float4 v = ((const float4*)(X + (size_t)idx * D128))[lane];
        acc.x += wgt * v.x; acc.y += wgt * v.y;
        acc.z += wgt * v.z; acc.w += wgt * v.w;
        cnt += wgt;
    }
    float inv = 1.0f / fmaxf(cnt, 1.f);
    acc.x *= inv; acc.y *= inv; acc.z *= inv; acc.w *= inv;
    ((float4*)(mean + (size_t)w * D128))[lane] = acc;
}

// ---------------- weight pre-split: [Wl;Wr] -> tf32 hi/lo in global ----------------
__global__ void k_splitB(const float* __restrict__ Wl, const float* __restrict__ Wr,
                         float* __restrict__ bh, float* __restrict__ bl) {
    int i = blockIdx.x * blockDim.x + threadIdx.x;   // 32768
    float v = (i < 16384) ? Wl[i] : Wr[i - 16384];
    uint32_t hi, lo;
    tf32_split(v, hi, lo);
    bh[i] = __uint_as_float(hi);
    bl[i] = __uint_as_float(lo);
}

// ---------------- tf32 mma GEMM: H = relu([mean|x] @ [Wl;Wr] + bl) ----------------
// CTA tile 128x128, K=256 in 16 chunks of 16. A split at SMEM-store; B pre-split.
#define ACH 16
#define ASTR 20
#define BSTR 136

__global__ void __launch_bounds__(256, 2)
k_gemm_mma(const float* __restrict__ Am, const float* __restrict__ Ax,
           const float* __restrict__ Bhi, const float* __restrict__ Blo,
           const float* __restrict__ bias, float* __restrict__ H, int n) {
    __shared__ float Ah[128 * ASTR];
    __shared__ float Al[128 * ASTR];
    __shared__ float Bh[ACH * BSTR];
    __shared__ float Bl[ACH * BSTR];
    int t = threadIdx.x, lane = t & 31, wid = t >> 5;
    int wm = (wid >> 2) * 64;
    int wn = (wid & 3) * 32;
    int m0 = blockIdx.x * 128;

    float c[4][4][4];
#pragma unroll
    for (int i = 0; i < 4; i++)
#pragma unroll
        for (int j = 0; j < 4; j++)
#pragma unroll
            for (int r = 0; r < 4; r++) c[i][j][r] = 0.f;

    int arow = t >> 1, acol0 = (t & 1) * 8;
    int brow = t >> 4, bcol0 = (t & 15) * 8;

    for (int ch = 0; ch < 16; ch++) {
        // A chunk [128 x 16], split at store
        const float* A = (ch < 8) ? Am + (size_t)m0 * D128 + ch * ACH
                                  : Ax + (size_t)m0 * D128 + (ch - 8) * ACH;
#pragma unroll
        for (int q = 0; q < 2; q++) {
            float4 v = *(const float4*)(A + (size_t)arow * D128 + acol0 + q * 4);
            uint32_t h0, h1, h2, h3, l0, l1, l2, l3;
            tf32_split(v.x, h0, l0); tf32_split(v.y, h1, l1);
            tf32_split(v.z, h2, l2); tf32_split(v.w, h3, l3);
            float4 hv = make_float4(__uint_as_float(h0), __uint_as_float(h1),
                                    __uint_as_float(h2), __uint_as_float(h3));
            float4 lv = make_float4(__uint_as_float(l0), __uint_as_float(l1),
                                    __uint_as_float(l2), __uint_as_float(l3));
            *(float4*)(Ah + arow * ASTR + acol0 + q * 4) = hv;
            *(float4*)(Al + arow * ASTR + acol0 + q * 4) = lv;
        }
        // B chunk [16 x 128], pre-split in global
#pragma unroll
        for (int q = 0; q < 2; q++) {
            *(float4*)(Bh + brow * BSTR + bcol0 + q * 4) =
                *(const float4*)(Bhi + (size_t)(ch * ACH + brow) * D128 + bcol0 + q * 4);
            *(float4*)(Bl + brow * BSTR + bcol0 + q * 4) =
                *(const float4*)(Blo + (size_t)(ch * ACH + brow) * D128 + bcol0 + q * 4);
        }
        __syncthreads();

#pragma unroll
        for (int ks = 0; ks < 2; ks++) {
            uint32_t ah[4][4], bh[4][2];
            // phase 1: hi*hi
#pragma unroll
            for (int mf = 0; mf < 4; mf++)
#pragma unroll
                for (int r = 0; r < 4; r++)
                    ah[mf][r] = __float_as_uint(
                        Ah[(wm + mf * 16 + (lane >> 2) + 8 * (r & 1)) * ASTR
                           + ks * 8 + (lane & 3) + 4 * (r >> 1)]);
#pragma unroll
            for (int nf = 0; nf < 4; nf++)
#pragma unroll
                for (int r = 0; r < 2; r++)
                    bh[nf][r] = __float_as_uint(
                        Bh[(ks * 8 + (lane & 3) + 4 * r) * BSTR + wn + nf * 8 + (lane >> 2)]);
#pragma unroll
            for (int mf = 0; mf < 4; mf++)
#pragma unroll
                for (int nf = 0; nf < 4; nf++)
                    mma_m16n8k8(c[mf][nf], ah[mf], bh[nf]);
            // phase 2: hi*lo
            {
                uint32_t blo[4][2];
#pragma unroll
                for (int nf = 0; nf < 4; nf++)
#pragma unroll
                    for (int r = 0; r < 2; r++)
                        blo[nf][r] = __float_as_uint(
                            Bl[(ks * 8 + (lane & 3) + 4 * r) * BSTR + wn + nf * 8 + (lane >> 2)]);
#pragma unroll
                for (int mf = 0; mf < 4; mf++)
#pragma unroll
                    for (int nf = 0; nf < 4; nf++)
                        mma_m16n8k8(c[mf][nf], ah[mf], blo[nf]);
            }
            // phase 3: lo*hi
            {
                uint32_t al[4][4];
#pragma unroll
                for (int mf = 0; mf < 4; mf++)
#pragma unroll
                    for (int r = 0; r < 4; r++)
                        al[mf][r] = __float_as_uint(
                            Al[(wm + mf * 16 + (lane >> 2) + 8 * (r & 1)) * ASTR
                               + ks * 8 + (lane & 3) + 4 * (r >> 1)]);
#pragma unroll
                for (int mf = 0; mf < 4; mf++)
#pragma unroll
                    for (int nf = 0; nf < 4; nf++)
                        mma_m16n8k8(c[mf][nf], al[mf], bh[nf]);
            }
        }
        __syncthreads();
    }

    // epilogue: bias + relu
    int r0 = lane >> 2, cq = (lane & 3) * 2;
#pragma unroll
    for (int mf = 0; mf < 4; mf++) {
        int row = m0 + wm + mf * 16 + r0;
#pragma unroll
        for (int nf = 0; nf < 4; nf++) {
            int col = wn + nf * 8 + cq;
            float b0 = bias[col], b1 = bias[col + 1];
            float2 o0, o1;
            o0.x = fmaxf(c[mf][nf][0] + b0, 0.f);
            o0.y = fmaxf(c[mf][nf][1] + b1, 0.f);
            o1.x = fmaxf(c[mf][nf][2] + b0, 0.f);
            o1.y = fmaxf(c[mf][nf][3] + b1, 0.f);
            *(float2*)(H + (size_t)row * D128 + col) = o0;
            *(float2*)(H + (size_t)(row + 8) * D128 + col) = o1;
        }
    }
}

// score[i] = tanh(h_i . pw / ||pw||), one warp per row
__global__ void k_score(const float* __restrict__ H, const float* __restrict__ pw,
                        float* __restrict__ score, int n) {
    int w = (blockIdx.x * blockDim.x + threadIdx.x) >> 5;
    int lane = threadIdx.x & 31;
    if (w >= n) return;
    float4 h4 = ((const float4*)(H + (size_t)w * D128))[lane];
    float4 w4 = ((const float4*)pw)[lane];
    float dot = h4.x * w4.x + h4.y * w4.y + h4.z * w4.z + h4.w * w4.w;
    float nn = w4.x * w4.x + w4.y * w4.y + w4.z * w4.z + w4.w * w4.w;
#pragma unroll
    for (int off = 16; off > 0; off >>= 1) {
        dot += __shfl_xor_sync(0xFFFFFFFF, dot, off);
        nn  += __shfl_xor_sync(0xFFFFFFFF, nn, off);
    }
    if (lane == 0) score[w] = tanhf(dot / sqrtf(nn));
}

// per-graph bitonic top-K (1024 threads)
__global__ void k_topk(const float* __restrict__ score, const float* __restrict__ H,
                       float* __restrict__ pool, int* __restrict__ newid, int Npg, int K) {
    __shared__ float skey[1024];
    __shared__ int   sidx[1024];
    int g = blockIdx.x;
    int t = threadIdx.x;   // 1024 threads
    skey[t] = (t < Npg) ? score[g * Npg + t] : -INFINITY;
    sidx[t] = t;
    __syncthreads();
    for (int k = 2; k <= 1024; k <<= 1) {
        for (int j = k >> 1; j > 0; j >>= 1) {
            int ixj = t ^ j;
            if (ixj > t) {
                bool desc = ((t & k) == 0);
                float a = skey[t], b = skey[ixj];
                bool sw = desc ? (a < b) : (a > b);
                if (sw) {
                    skey[t] = b; skey[ixj] = a;
                    int tmp = sidx[t]; sidx[t] = sidx[ixj]; sidx[ixj] = tmp;
                }
            }
            __syncthreads();
        }
    }
    if (t < Npg) {
        int node = sidx[t];
        newid[g * Npg + node] = (t < K) ? (g * K + t) : -1;
    }
    __syncthreads();
    int total = K * D128;
    for (int l = t; l < total; l += 1024) {
        int r = l >> 7, f = l & 127;
        int node = sidx[r];
        pool[(size_t)(g * K + r) * D128 + f] =
            H[(size_t)(g * Npg + node) * D128 + f] * skey[r];
    }
}

// readout: s[g] (+)= [max || mean]; 512 threads, 4-way row split
__global__ void k_readout(const float* __restrict__ pool, int K, float* __restrict__ s_out,
                          int round) {
    __shared__ float smx[4][128];
    __shared__ float ssm[4][128];
    int g = blockIdx.x, t = threadIdx.x;
    int f = t & 127, part = t >> 7;
    float mx = -INFINITY, sm = 0.f;
    for (int r = part; r < K; r += 4) {
        float v = pool[(size_t)(g * K + r) * D128 + f];
        mx = fmaxf(mx, v);
        sm += v;
    }
    smx[part][f] = mx; ssm[part][f] = sm;
    __syncthreads();
    if (part == 0) {
        float m2 = fmaxf(fmaxf(smx[0][f], smx[1][f]), fmaxf(smx[2][f], smx[3][f]));
        float s2 = ssm[0][f] + ssm[1][f] + ssm[2][f] + ssm[3][f];
        float mean = s2 / (float)K;
        if (round == 0) {
            s_out[g * 256 + f] = m2;
            s_out[g * 256 + 128 + f] = mean;
        } else {
            s_out[g * 256 + f] += m2;
            s_out[g * 256 + 128 + f] += mean;
        }
    }
}

// final MLP: 256->128->64->1 + sigmoid
__global__ void k_mlp(const float* __restrict__ s,
                      const float* __restrict__ W1, const float* __restrict__ b1,
                      const float* __restrict__ W2, const float* __restrict__ b2,
                      const float* __restrict__ W3, const float* __restrict__ b3,
                      float* __restrict__ out) {
    __shared__ float sh[256];
    __shared__ float h1[128];
    __shared__ float h2[64];
    __shared__ float red[128];
    int g = blockIdx.x, t = threadIdx.x;
    sh[t] = s[g * 256 + t];
    sh[t + 128] = s[g * 256 + 128 + t];
    __syncthreads();
    float acc = b1[t];
    for (int k = 0; k < 256; k++) acc += sh[k] * W1[k * 128 + t];
    h1[t] = fmaxf(acc, 0.f);
    __syncthreads();
    if (t < 64) {
        float a = b2[t];
        for (int k = 0; k < 128; k++) a += h1[k] * W2[k * 64 + t];
        h2[t] = fmaxf(a, 0.f);
    }
    __syncthreads();
    red[t] = (t < 64) ? h2[t] * W3[t] : 0.f;
    __syncthreads();
    for (int off = 64; off > 0; off >>= 1) {
        if (t < off) red[t] += red[t + off];
        __syncthreads();
    }
    if (t == 0) out[g] = 1.f / (1.f + expf(-(red[0] + b3[0])));
}

// ---------------- host orchestration ----------------
extern "C" void kernel_launch(void* const* d_in, const int* in_sizes, int n_in,
                              void* d_out, int out_size) {
    const float* x   = (const float*)d_in[0];
    const int*   ei  = (const int*)d_in[1];
    const int E = in_sizes[1] / 2;

    const float* Wl1 = (const float*)d_in[2];
    const float* bl1 = (const float*)d_in[3];
    const float* Wr1 = (const float*)d_in[4];
    const float* pw1 = (const float*)d_in[5];
    const float* Wl2 = (const float*)d_in[6];
    const float* bl2 = (const float*)d_in[7];
    const float* Wr2 = (const float*)d_in[8];
    const float* pw2 = (const float*)d_in[9];
    const float* Wl3 = (const float*)d_in[10];
    const float* bl3 = (const float*)d_in[11];
    const float* Wr3 = (const float*)d_in[12];
    const float* pw3 = (const float*)d_in[13];
    const float* W1  = (const float*)d_in[14];
    const float* b1  = (const float*)d_in[15];
    const float* W2  = (const float*)d_in[16];
    const float* b2  = (const float*)d_in[17];
    const float* W3  = (const float*)d_in[18];
    const float* b3  = (const float*)d_in[19];

    float *meanP, *hP, *poolA, *poolB, *scoreP, *sP, *bhiP, *bloP;
    int *newidP, *o2cP, *c2oP, *degP, *curP, *rpP, *nbrP, *partP, *offsP;
    cudaGetSymbolAddress((void**)&meanP, g_mean);
    cudaGetSymbolAddress((void**)&hP, g_h);
    cudaGetSymbolAddress((void**)&poolA, g_poolA);
    cudaGetSymbolAddress((void**)&poolB, g_poolB);
    cudaGetSymbolAddress((void**)&scoreP, g_score);
    cudaGetSymbolAddress((void**)&sP, g_s);
    cudaGetSymbolAddress((void**)&bhiP, g_bhi);
    cudaGetSymbolAddress((void**)&bloP, g_blo);
    cudaGetSymbolAddress((void**)&newidP, g_newid);
    cudaGetSymbolAddress((void**)&o2cP, g_orig2cur);
    cudaGetSymbolAddress((void**)&c2oP, g_cur2orig);
    cudaGetSymbolAddress((void**)&degP, g_deg);
    cudaGetSymbolAddress((void**)&curP, g_cursor);
    cudaGetSymbolAddress((void**)&rpP, g_rowptr);
    cudaGetSymbolAddress((void**)&nbrP, g_nbr);
    cudaGetSymbolAddress((void**)&partP, g_part);
    cudaGetSymbolAddress((void**)&offsP, g_offs);

    const int TB = 256;
    const int EB = (E + TB - 1) / TB;
    const int n0 = NMAX;

    // ---- one-time CSR build on original graph ----
    k_zero_int<<<(n0 + TB - 1) / TB, TB>>>(degP, n0);
    k_count<<<EB, TB>>>(ei + E, E, degP);
    k_scan1<<<64, 1024>>>(degP, partP);
    k_scan2<<<1, 64>>>(partP, offsP);
    k_scan3<<<64, 1024>>>(degP, offsP, rpP, curP, n0);
    k_scatter<<<EB, TB>>>(ei, ei + E, E, curP, nbrP);
    k_initmaps<<<(n0 + TB - 1) / TB, TB>>>(o2cP, c2oP);

    struct LayerCfg {
        const float *xin, *Wl, *bl, *Wr, *pw;
        float* pool;
        int n, Npg, K, round;
    };
    LayerCfg layers[3] = {
        { x,     Wl1, bl1, Wr1, pw1, poolA, BGR * NPG0, NPG0, K1, 0 },
        { poolA, Wl2, bl2, Wr2, pw2, poolB, BGR * K1,   K1,   K2, 1 },
        { poolB, Wl3, bl3, Wr3, pw3, poolA, BGR * K2,   K2,   K3, 2 },
    };

    for (int L = 0; L < 3; L++) {
        LayerCfg& c = layers[L];
        int n = c.n;
        // weight pre-split
        k_splitB<<<128, 256>>>(c.Wl, c.Wr, bhiP, bloP);
        // mean aggregation over original CSR with alive masks
        k_aggregate<<<(n * 32 + TB - 1) / TB, TB>>>(c.xin, rpP, nbrP, c2oP, o2cP, meanP, n);
        // SAGE linear + relu (tf32 mma, 3x split)
        k_gemm_mma<<<n / 128, 256>>>(meanP, c.xin, bhiP, bloP, c.bl, hP, n);
        // topk score
        k_score<<<(n * 32 + TB - 1) / TB, TB>>>(hP, c.pw, scoreP, n);
        // pooling
        k_topk<<<BGR, 1024>>>(scoreP, hP, c.pool, newidP, c.Npg, c.K);
        // update survival maps
        if (L < 2) k_compose<<<(n0 + TB - 1) / TB, TB>>>(o2cP, c2oP, newidP);
        // readout accumulate
        k_readout<<<BGR, 512>>>(c.pool, c.K, sP, c.round);
    }

    k_mlp<<<BGR, 128>>>(sP, W1, b1, W2, b2, W3, b3, (float*)d_out);
}